// round 15
// baseline (speedup 1.0000x reference)
#include <cuda_runtime.h>
#include <cuda_bf16.h>
#include <mma.h>
#include <cstdint>

using namespace nvcuda;

#define TBG   512
#define TIN   256
#define MROWS 2048      // B*N = 32*64

#define BM    64
#define BI    64
#define LDW   520       // padded bf16 leading dim (1040B rows, conflict-free)
#define LDP   68        // padded f32 leading dim for partial tiles

// smem layout (dynamic):
//   As  : BM x LDW bf16                    [0, 66560)
//   Ws  : BI x LDW bf16                    [66560, 133120)
//   q   : 512 float4 (u, e^-bu, e^+bu, 0)  [133120, 141312)
//   tin : 64 float                         [141312, 141568)
//   Ps[4]: 4 x (BM x LDP f32) partials, ALIAS over As+Ws (dead after MMA)
#define AS_BYTES   (BM * LDW * 2)
#define WS_OFF     AS_BYTES
#define WS_BYTES   (BI * LDW * 2)
#define Q_OFF      (WS_OFF + WS_BYTES)
#define TIN_OFF    (Q_OFF + TBG * 16)
#define SMEM_TOTAL (TIN_OFF + BI * 4)
#define PS_BYTES   (BM * LDP * 4)       // 17408; 4x = 69632 < As+Ws (133120)

__global__ void __launch_bounds__(512, 1)
fused_kernel(const float* __restrict__ surv,
             const float* __restrict__ time_bg,
             const float* __restrict__ time_in,
             const float* __restrict__ bandwidth,
             float* __restrict__ C) {
    extern __shared__ char smem[];
    __nv_bfloat16* As  = reinterpret_cast<__nv_bfloat16*>(smem);
    __nv_bfloat16* Ws  = reinterpret_cast<__nv_bfloat16*>(smem + WS_OFF);
    float4*        q   = reinterpret_cast<float4*>(smem + Q_OFF);
    float*         tin = reinterpret_cast<float*>(smem + TIN_OFF);

    const int tid = threadIdx.x;
    const int wid = tid >> 5;
    const int lid = tid & 31;

    const int i0 = blockIdx.x * BI;   // output col block (T_in)
    const int m0 = blockIdx.y * BM;   // output row block (B*N)

    const float b = fmaxf(bandwidth[0], 1e-6f);

    // ---- 1. prefetch time_in block + exp table (one t per thread) ----
    if (tid < BI) tin[tid] = time_in[i0 + tid];
    {
        const float u = time_bg[tid];
        q[tid] = make_float4(u, __expf(-b * u), __expf(b * u), 0.0f);
    }

    // ---- 2. A tile [BM x 512] fp32 -> bf16 smem (16 float4 / thread) ----
    {
        const float* Ag = surv + (size_t)m0 * TBG;
        #pragma unroll
        for (int it = 0; it < 16; it++) {
            const int idx = it * 512 + tid;    // 8192 float4 total
            const int r   = idx >> 7;          // 0..63
            const int c4  = idx & 127;
            const float4 v = *reinterpret_cast<const float4*>(Ag + (size_t)r * TBG + c4 * 4);
            __nv_bfloat162 p0 = __floats2bfloat162_rn(v.x, v.y);
            __nv_bfloat162 p1 = __floats2bfloat162_rn(v.z, v.w);
            uint2 o;
            o.x = *reinterpret_cast<unsigned int*>(&p0);
            o.y = *reinterpret_cast<unsigned int*>(&p1);
            *reinterpret_cast<uint2*>(&As[r * LDW + c4 * 4]) = o;
        }
    }
    __syncthreads();   // q, tin, As ready

    // ---- 3. softmin weights: q rows hoisted into registers, reused 4x ----
    // raw_t = (u_t >= v) ? e^{-b u_t} : e^{+b u_t} * e^{-2 b v}
    {
        float qu[16], qp[16], qn[16];
        #pragma unroll
        for (int j = 0; j < 16; j++) {
            const float4 qq = q[j * 32 + lid];   // one 8KB sweep per WARP, once
            qu[j] = qq.x; qp[j] = qq.y; qn[j] = qq.z;
        }

        #pragma unroll 1
        for (int ii = 0; ii < 4; ii++) {
            const int i   = wid * 4 + ii;            // local i 0..63
            const float v = tin[i];
            const float g = __expf(-2.0f * b * v);

            float sm = 0.0f;
            #pragma unroll
            for (int j = 0; j < 16; j++)
                sm += (qu[j] >= v) ? qp[j] : qn[j] * g;
            #pragma unroll
            for (int o = 16; o > 0; o >>= 1)
                sm += __shfl_xor_sync(0xffffffffu, sm, o);

            const float inv = __fdividef(1.0f, sm);
            #pragma unroll
            for (int j = 0; j < 16; j++) {
                const float w = (qu[j] >= v) ? qp[j] : qn[j] * g;
                Ws[i * LDW + j * 32 + lid] = __float2bfloat16(w * inv);
            }
        }
    }
    __syncthreads();

    // ---- 4. MMA, k-split x4: warp group wk = wid>>2 owns k [wk*128, +128)
    //         per quarter: 4 warps as 2m x 2i, warp tile 32m x 32i (2x2 frags)
    const int wk = wid >> 2;         // 0..3
    const int w4 = wid & 3;
    const int wm = w4 >> 1;          // 0..1
    const int wi = w4 & 1;           // 0..1

    wmma::fragment<wmma::accumulator, 16, 16, 16, float> acc[2][2];
    #pragma unroll
    for (int fm = 0; fm < 2; fm++)
        #pragma unroll
        for (int fi = 0; fi < 2; fi++)
            wmma::fill_fragment(acc[fm][fi], 0.0f);

    {
        const __nv_bfloat16* a_base = &As[(wm * 32) * LDW + wk * 128];
        const __nv_bfloat16* b_base = &Ws[(wi * 32) * LDW + wk * 128];

        #pragma unroll 8
        for (int kk = 0; kk < 128; kk += 16) {
            wmma::fragment<wmma::matrix_a, 16, 16, 16, __nv_bfloat16, wmma::row_major> af[2];
            wmma::fragment<wmma::matrix_b, 16, 16, 16, __nv_bfloat16, wmma::col_major> bf[2];
            wmma::load_matrix_sync(af[0], a_base + kk, LDW);
            wmma::load_matrix_sync(af[1], a_base + 16 * LDW + kk, LDW);
            wmma::load_matrix_sync(bf[0], b_base + kk, LDW);
            wmma::load_matrix_sync(bf[1], b_base + 16 * LDW + kk, LDW);
            #pragma unroll
            for (int fm = 0; fm < 2; fm++)
                #pragma unroll
                for (int fi = 0; fi < 2; fi++)
                    wmma::mma_sync(acc[fm][fi], af[fm], bf[fi], acc[fm][fi]);
        }
    }

    // ---- 5. parallel reduction: all groups store partials, all warps sum ----
    __syncthreads();    // all MMA smem reads done; As/Ws now dead
    {
        float* Ps = reinterpret_cast<float*>(smem + wk * PS_BYTES);
        #pragma unroll
        for (int fm = 0; fm < 2; fm++)
            #pragma unroll
            for (int fi = 0; fi < 2; fi++)
                wmma::store_matrix_sync(
                    &Ps[(wm * 32 + fm * 16) * LDP + wi * 32 + fi * 16],
                    acc[fm][fi], LDP, wmma::mem_row_major);
    }
    __syncthreads();
    {
        // each thread: 2 consecutive float4 of the 64x64 tile, summed over 4 Ps
        #pragma unroll
        for (int e = 0; e < 2; e++) {
            const int f = tid * 2 + e;        // 0..1023 float4 index
            const int r = f >> 4;             // 0..63
            const int c = f & 15;             // float4 col
            float4 s = make_float4(0.f, 0.f, 0.f, 0.f);
            #pragma unroll
            for (int sgrp = 0; sgrp < 4; sgrp++) {
                const float4 p = *reinterpret_cast<const float4*>(
                    smem + sgrp * PS_BYTES + (r * LDP + c * 4) * 4);
                s.x += p.x; s.y += p.y; s.z += p.z; s.w += p.w;
            }
            *reinterpret_cast<float4*>(C + (size_t)(m0 + r) * TIN + i0 + c * 4) = s;
        }
    }
}

// ===========================================================================
extern "C" void kernel_launch(void* const* d_in, const int* in_sizes, int n_in,
                              void* d_out, int out_size) {
    const float* surv      = (const float*)d_in[0];
    const float* time_bg   = (const float*)d_in[1];
    const float* time_in   = (const float*)d_in[2];
    const float* bandwidth = (const float*)d_in[3];
    float*       out       = (float*)d_out;

    static bool attr_done = false;
    if (!attr_done) {
        cudaFuncSetAttribute(fused_kernel,
                             cudaFuncAttributeMaxDynamicSharedMemorySize, SMEM_TOTAL);
        attr_done = true;
    }

    dim3 grid(TIN / BI, MROWS / BM);   // (4, 32) = 128 CTAs, 1 wave
    fused_kernel<<<grid, 512, SMEM_TOTAL>>>(surv, time_bg, time_in, bandwidth, out);
}